// round 14
// baseline (speedup 1.0000x reference)
#include <cuda_runtime.h>
#include <math.h>

// Problem constants
#define Nn 8
#define Cc 8
#define Tt 600
#define Ff 257
#define NCHUNK 12
#define TCHUNK 50               // Tt / NCHUNK
#define LOADC 7.0710678118654754e-04f   // 0.001/sqrt(2)
#define TFv (Tt * Ff)           // 154200
#define HTF (TFv / 2)           // 77100  (t and t+300 share f)

// Scratch (device globals — no allocation allowed)
__device__ __align__(16) float g_phi[(size_t)NCHUNK * Nn * 72 * Ff];
__device__ __align__(16) float g_w16[(size_t)Nn * Ff * 16];   // [n][f][2c(+1)] interleaved conj(w)

// ---- packed f32x2 helpers (Blackwell FFMA2) --------------------------------
__device__ __forceinline__ unsigned long long pk2(float lo, float hi) {
    unsigned long long r;
    asm("mov.b64 %0, {%1, %2};" : "=l"(r) : "f"(lo), "f"(hi));
    return r;
}
__device__ __forceinline__ void fma2(unsigned long long& d, unsigned long long a, unsigned long long b) {
    asm("fma.rn.f32x2 %0, %1, %2, %0;" : "+l"(d) : "l"(a), "l"(b));
}
__device__ __forceinline__ void unpk2(unsigned long long v, float& lo, float& hi) {
    asm("mov.b64 {%0, %1}, %2;" : "=f"(lo), "=f"(hi) : "l"(v));
}

// upper-tri pair index for c<=d
#define PIDX(c, d) ((c) * 8 - (c) * ((c) - 1) / 2 + ((d) - (c)))

// ---------------------------------------------------------------------------
// Kernel 1: partial noise covariance, packed-FMA complex MACs.
// Grid: (3, NCHUNK, Nn) x 128.
// ---------------------------------------------------------------------------
__global__ void __launch_bounds__(128) cov_kernel(const float* __restrict__ noise) {
    int f = blockIdx.x * 128 + threadIdx.x;
    if (f >= Ff) return;
    int chunk = blockIdx.y;
    int n = blockIdx.z;

    const size_t TF = (size_t)TFv;
    const float* vr = noise + (size_t)n * 2 * Cc * TF + (size_t)(chunk * TCHUNK) * Ff + f;
    const float* vi = vr + Cc * TF;

    unsigned long long acc[36];
#pragma unroll
    for (int j = 0; j < 36; j++) acc[j] = 0ULL;

#pragma unroll 2
    for (int t = 0; t < TCHUNK; t++) {
        float yr[8], yi[8];
#pragma unroll
        for (int c = 0; c < 8; c++) {
            yr[c] = vr[c * TF + (size_t)t * Ff];
            yi[c] = vi[c * TF + (size_t)t * Ff];
        }
        unsigned long long a1[8], a2[8];
#pragma unroll
        for (int c = 0; c < 8; c++) {
            a1[c] = pk2(yr[c], yi[c]);
            a2[c] = pk2(yi[c], -yr[c]);
        }
#pragma unroll
        for (int d = 0; d < 8; d++) {
            unsigned long long bR = pk2(yr[d], yr[d]);
            unsigned long long bI = pk2(yi[d], yi[d]);
#pragma unroll
            for (int c = 0; c <= d; c++) {
                fma2(acc[PIDX(c, d)], a1[c], bR);
                fma2(acc[PIDX(c, d)], a2[c], bI);
            }
        }
    }

    float* out = g_phi + ((size_t)(chunk * Nn + n) * 72) * Ff + f;
#pragma unroll
    for (int p = 0; p < 36; p++) {
        float re, im;
        unpk2(acc[p], re, im);
        out[(size_t)(2 * p) * Ff]     = re;
        out[(size_t)(2 * p + 1) * Ff] = im;
    }
}

// ---------------------------------------------------------------------------
// Kernel 2: warp-cooperative 8x8 complex solve with fused chunk reduction.
// 8 lanes per (n,f) problem; each lane sums its 18 covariance scalars over
// the NCHUNK partials directly (no separate reduce kernel / buffer).
// ---------------------------------------------------------------------------
struct C2 { float r, i; };
__device__ __forceinline__ C2 cmul(C2 a, C2 b) { return C2{a.r * b.r - a.i * b.i, a.r * b.i + a.i * b.r}; }
__device__ __forceinline__ C2 csub(C2 a, C2 b) { return C2{a.r - b.r, a.i - b.i}; }
__device__ __forceinline__ C2 cinv(C2 a) {
    float s = __frcp_rn(a.r * a.r + a.i * a.i);
    return C2{a.r * s, -a.i * s};
}
__device__ __forceinline__ C2 bcast8(unsigned mask, C2 v, int src) {
    return C2{__shfl_sync(mask, v.r, src, 8), __shfl_sync(mask, v.i, src, 8)};
}

__global__ void __launch_bounds__(256) solve_kernel(const float* __restrict__ sv) {
    int gid = blockIdx.x * 256 + threadIdx.x;
    int r = gid & 7;
    int prob = gid >> 3;
    if (prob >= Nn * Ff) prob = Nn * Ff - 1;   // clamp: dup groups write same values
    int n = prob / Ff;
    int f = prob - n * Ff;
    const unsigned mask = 0xFFFFFFFFu;

    const float invT = 1.0f / (float)Tt;
    const int CHSTRIDE = Nn * 72 * Ff;          // floats per chunk slab

    C2 row[9];
#pragma unroll
    for (int c = 0; c < 8; c++) {
        int a = (r < c) ? r : c;
        int b = (r < c) ? c : r;
        int p = a * 8 - a * (a - 1) / 2 + (b - a);
        const float* srcR = g_phi + ((size_t)n * 72 + 2 * p) * Ff + f;
        const float* srcI = srcR + Ff;
        float re = 0.f, im = 0.f;
#pragma unroll
        for (int ch = 0; ch < NCHUNK; ch++) {
            re += srcR[(size_t)ch * CHSTRIDE];
            im += srcI[(size_t)ch * CHSTRIDE];
        }
        re *= invT;
        im *= invT;
        if (c < r) im = -im;
        if (c == r) { re += LOADC; im += LOADC; }
        row[c] = C2{re, im};
    }
    const float* dr = sv + ((size_t)n * 2 * Ff + f) * Cc;
    C2 dn = C2{dr[r], dr[(size_t)Ff * Cc + r]};
    row[8] = dn;

#pragma unroll
    for (int k = 0; k < 8; k++) {
        C2 piv = bcast8(mask, row[k], k);
        C2 fac = cmul(row[k], cinv(piv));
#pragma unroll
        for (int col = k + 1; col < 9; col++) {
            C2 pk = bcast8(mask, row[col], k);
            if (r > k) row[col] = csub(row[col], cmul(fac, pk));
        }
    }

    C2 s = row[8];
    C2 myx = C2{0.f, 0.f};
#pragma unroll
    for (int k = 7; k >= 0; k--) {
        C2 sk = bcast8(mask, s, k);
        C2 dk = bcast8(mask, row[k], k);
        C2 xk = cmul(sk, cinv(dk));
        if (r == k) myx = xk;
        if (r < k) s = csub(s, cmul(row[k], xk));
    }

    C2 term = C2{dn.r * myx.r + dn.i * myx.i, dn.r * myx.i - dn.i * myx.r};
#pragma unroll
    for (int off = 4; off; off >>= 1) {
        term.r += __shfl_xor_sync(mask, term.r, off, 8);
        term.i += __shfl_xor_sync(mask, term.i, off, 8);
    }
    C2 w = cmul(myx, cinv(term));

    float* wout = g_w16 + ((size_t)n * Ff + f) * 16;
    wout[2 * r]     = w.r;
    wout[2 * r + 1] = -w.i;
}

// ---------------------------------------------------------------------------
// Kernel 3: beamform — each thread does TWO elements sharing f (t and t+300),
// so the 4 weight LDG.128 amortize over both. Payload stays fully coalesced.
// Grid: (ceil(HTF/256), Nn).
// ---------------------------------------------------------------------------
__global__ void __launch_bounds__(256) bf_kernel(const float* __restrict__ mix,
                                                 float* __restrict__ out) {
    int p = blockIdx.x * 256 + threadIdx.x;
    if (p >= HTF) return;
    int n = blockIdx.y;
    int f = p % Ff;

    const float4* wrow = (const float4*)(g_w16 + ((size_t)n * Ff + f) * 16);
    float4 w0 = wrow[0], w1 = wrow[1], w2 = wrow[2], w3 = wrow[3];
    float wr[8] = {w0.x, w0.z, w1.x, w1.z, w2.x, w2.z, w3.x, w3.z};
    float wi[8] = {w0.y, w0.w, w1.y, w1.w, w2.y, w2.w, w3.y, w3.w};

    const float* mbase = mix + (size_t)n * 2 * Cc * TFv;
    float* obase = out + (size_t)n * 2 * TFv;

#pragma unroll
    for (int e = 0; e < 2; e++) {
        int pe = p + e * HTF;
        const float* base = mbase + pe;
        float Xr = 0.f, Xi = 0.f;
#pragma unroll
        for (int c = 0; c < 8; c++) {
            float yr = base[(size_t)c * TFv];
            float yv = base[(size_t)(Cc + c) * TFv];
            Xr += wr[c] * yr - wi[c] * yv;
            Xi += wr[c] * yv + wi[c] * yr;
        }
        obase[pe]       = Xr;
        obase[pe + TFv] = Xi;
    }
}

// ---------------------------------------------------------------------------
extern "C" void kernel_launch(void* const* d_in, const int* in_sizes, int n_in,
                              void* d_out, int out_size) {
    const float* mixture = (const float*)d_in[0];
    const float* noise   = (const float*)d_in[1];
    const float* sv      = (const float*)d_in[2];
    float* out = (float*)d_out;

    // 1. partial covariance over noise
    dim3 g1((Ff + 127) / 128, NCHUNK, Nn);
    cov_kernel<<<g1, 128>>>(noise);

    // 2. fused reduce + warp-cooperative solve: 8 lanes per (n,f)
    int sthreads = Nn * Ff * 8;
    solve_kernel<<<(sthreads + 255) / 256, 256>>>(sv);

    // 3. beamform: two elements per thread (shared weights), grid.y = n
    dim3 g3((HTF + 255) / 256, Nn);
    bf_kernel<<<g3, 256>>>(mixture, out);
}

// round 15
// speedup vs baseline: 1.2147x; 1.2147x over previous
#include <cuda_runtime.h>
#include <math.h>

// Problem constants
#define Nn 8
#define Cc 8
#define Tt 600
#define Ff 257
#define NCHUNK 30
#define TCHUNK 20               // Tt / NCHUNK
#define LOADC 7.0710678118654754e-04f   // 0.001/sqrt(2)
#define TFv (Tt * Ff)           // 154200
#define HTF (TFv / 2)           // 77100  (t and t+300 share f)
#define GCOV (NCHUNK * Ff)      // 7710 dense (chunk,f) work items per n

// Scratch (device globals — no allocation allowed)
__device__ __align__(16) float g_phi[(size_t)NCHUNK * Nn * 72 * Ff];
__device__ __align__(16) float g_phired[(size_t)Nn * 72 * Ff];
__device__ __align__(16) float g_w16[(size_t)Nn * Ff * 16];   // [n][f][2c(+1)] interleaved conj(w)

// ---- packed f32x2 helpers (Blackwell FFMA2) --------------------------------
__device__ __forceinline__ unsigned long long pk2(float lo, float hi) {
    unsigned long long r;
    asm("mov.b64 %0, {%1, %2};" : "=l"(r) : "f"(lo), "f"(hi));
    return r;
}
__device__ __forceinline__ void fma2(unsigned long long& d, unsigned long long a, unsigned long long b) {
    asm("fma.rn.f32x2 %0, %1, %2, %0;" : "+l"(d) : "l"(a), "l"(b));
}
__device__ __forceinline__ void unpk2(unsigned long long v, float& lo, float& hi) {
    asm("mov.b64 {%0, %1}, %2;" : "=f"(lo), "=f"(hi) : "l"(v));
}

// upper-tri pair index for c<=d
#define PIDX(c, d) ((c) * 8 - (c) * ((c) - 1) / 2 + ((d) - (c)))

// one t-step of complex outer-product accumulation (packed FMAs)
__device__ __forceinline__ void cov_accum(unsigned long long* acc,
                                          const float* yr, const float* yi) {
    unsigned long long a1[8], a2[8];
#pragma unroll
    for (int c = 0; c < 8; c++) {
        a1[c] = pk2(yr[c], yi[c]);
        a2[c] = pk2(yi[c], -yr[c]);
    }
#pragma unroll
    for (int d = 0; d < 8; d++) {
        unsigned long long bR = pk2(yr[d], yr[d]);
        unsigned long long bI = pk2(yi[d], yi[d]);
#pragma unroll
        for (int c = 0; c <= d; c++) {
            fma2(acc[PIDX(c, d)], a1[c], bR);
            fma2(acc[PIDX(c, d)], a2[c], bI);
        }
    }
}

// ---------------------------------------------------------------------------
// Kernel 1: partial noise covariance.
// Dense (chunk,f) flattening — no near-empty f-tail blocks — plus
// double-buffered t-loads for 2x memory-level parallelism.
// Grid: (ceil(GCOV/128), Nn) x 128.
// ---------------------------------------------------------------------------
__global__ void __launch_bounds__(128) cov_kernel(const float* __restrict__ noise) {
    int g = blockIdx.x * 128 + threadIdx.x;
    if (g >= GCOV) return;
    int chunk = g / Ff;
    int f = g - chunk * Ff;
    int n = blockIdx.y;

    const size_t TF = (size_t)TFv;
    const float* vr = noise + (size_t)n * 2 * Cc * TF + (size_t)(chunk * TCHUNK) * Ff + f;
    const float* vi = vr + Cc * TF;

    unsigned long long acc[36];
#pragma unroll
    for (int j = 0; j < 36; j++) acc[j] = 0ULL;

    float yr[8], yi[8], zr[8], zi[8];
    // prefetch t = 0
#pragma unroll
    for (int c = 0; c < 8; c++) {
        yr[c] = vr[c * TF];
        yi[c] = vi[c * TF];
    }

#pragma unroll 1
    for (int t = 0; t < TCHUNK; t += 2) {
        // prefetch t+1 (always valid: TCHUNK even)
#pragma unroll
        for (int c = 0; c < 8; c++) {
            zr[c] = vr[c * TF + (size_t)(t + 1) * Ff];
            zi[c] = vi[c * TF + (size_t)(t + 1) * Ff];
        }
        cov_accum(acc, yr, yi);
        if (t + 2 < TCHUNK) {
#pragma unroll
            for (int c = 0; c < 8; c++) {
                yr[c] = vr[c * TF + (size_t)(t + 2) * Ff];
                yi[c] = vi[c * TF + (size_t)(t + 2) * Ff];
            }
        }
        cov_accum(acc, zr, zi);
    }

    float* out = g_phi + ((size_t)(chunk * Nn + n) * 72) * Ff + f;
#pragma unroll
    for (int p = 0; p < 36; p++) {
        float re, im;
        unpk2(acc[p], re, im);
        out[(size_t)(2 * p) * Ff]     = re;
        out[(size_t)(2 * p + 1) * Ff] = im;
    }
}

// ---------------------------------------------------------------------------
// Kernel 2: fold NCHUNK partials, float4-vectorized (high parallelism).
// ---------------------------------------------------------------------------
__global__ void __launch_bounds__(256) reduce_kernel() {
    const int total4 = (Nn * 72 * Ff) / 4;          // 37008
    int idx = blockIdx.x * 256 + threadIdx.x;
    if (idx >= total4) return;
    const float4* src = (const float4*)g_phi;
    float4 s = src[idx];
#pragma unroll
    for (int ch = 1; ch < NCHUNK; ch++) {
        float4 v = src[(size_t)ch * total4 + idx];
        s.x += v.x; s.y += v.y; s.z += v.z; s.w += v.w;
    }
    ((float4*)g_phired)[idx] = s;
}

// ---------------------------------------------------------------------------
// Kernel 3: warp-cooperative 8x8 complex solve (8 lanes per (n,f) problem).
// Reads the reduced covariance; writes conj(w) into g_w16[n][f][16].
// ---------------------------------------------------------------------------
struct C2 { float r, i; };
__device__ __forceinline__ C2 cmul(C2 a, C2 b) { return C2{a.r * b.r - a.i * b.i, a.r * b.i + a.i * b.r}; }
__device__ __forceinline__ C2 csub(C2 a, C2 b) { return C2{a.r - b.r, a.i - b.i}; }
__device__ __forceinline__ C2 cinv(C2 a) {
    float s = __frcp_rn(a.r * a.r + a.i * a.i);
    return C2{a.r * s, -a.i * s};
}
__device__ __forceinline__ C2 bcast8(unsigned mask, C2 v, int src) {
    return C2{__shfl_sync(mask, v.r, src, 8), __shfl_sync(mask, v.i, src, 8)};
}

__global__ void __launch_bounds__(256) solve_kernel(const float* __restrict__ sv) {
    int gid = blockIdx.x * 256 + threadIdx.x;
    int r = gid & 7;
    int prob = gid >> 3;
    if (prob >= Nn * Ff) prob = Nn * Ff - 1;   // clamp: dup groups write same values
    int n = prob / Ff;
    int f = prob - n * Ff;
    const unsigned mask = 0xFFFFFFFFu;

    const float invT = 1.0f / (float)Tt;
    const float* src = g_phired + (size_t)n * 72 * Ff + f;

    C2 row[9];
#pragma unroll
    for (int c = 0; c < 8; c++) {
        int a = (r < c) ? r : c;
        int b = (r < c) ? c : r;
        int p = a * 8 - a * (a - 1) / 2 + (b - a);
        float re = src[(size_t)(2 * p) * Ff] * invT;
        float im = src[(size_t)(2 * p + 1) * Ff] * invT;
        if (c < r) im = -im;
        if (c == r) { re += LOADC; im += LOADC; }
        row[c] = C2{re, im};
    }
    const float* dr = sv + ((size_t)n * 2 * Ff + f) * Cc;
    C2 dn = C2{dr[r], dr[(size_t)Ff * Cc + r]};
    row[8] = dn;

#pragma unroll
    for (int k = 0; k < 8; k++) {
        C2 piv = bcast8(mask, row[k], k);
        C2 fac = cmul(row[k], cinv(piv));
#pragma unroll
        for (int col = k + 1; col < 9; col++) {
            C2 pk = bcast8(mask, row[col], k);
            if (r > k) row[col] = csub(row[col], cmul(fac, pk));
        }
    }

    C2 s = row[8];
    C2 myx = C2{0.f, 0.f};
#pragma unroll
    for (int k = 7; k >= 0; k--) {
        C2 sk = bcast8(mask, s, k);
        C2 dk = bcast8(mask, row[k], k);
        C2 xk = cmul(sk, cinv(dk));
        if (r == k) myx = xk;
        if (r < k) s = csub(s, cmul(row[k], xk));
    }

    C2 term = C2{dn.r * myx.r + dn.i * myx.i, dn.r * myx.i - dn.i * myx.r};
#pragma unroll
    for (int off = 4; off; off >>= 1) {
        term.r += __shfl_xor_sync(mask, term.r, off, 8);
        term.i += __shfl_xor_sync(mask, term.i, off, 8);
    }
    C2 w = cmul(myx, cinv(term));

    float* wout = g_w16 + ((size_t)n * Ff + f) * 16;
    wout[2 * r]     = w.r;
    wout[2 * r + 1] = -w.i;
}

// ---------------------------------------------------------------------------
// Kernel 4: beamform — two elements per thread sharing f (t and t+300),
// weight LDG.128s amortized over both. Payload fully coalesced.
// Grid: (ceil(HTF/256), Nn).
// ---------------------------------------------------------------------------
__global__ void __launch_bounds__(256) bf_kernel(const float* __restrict__ mix,
                                                 float* __restrict__ out) {
    int p = blockIdx.x * 256 + threadIdx.x;
    if (p >= HTF) return;
    int n = blockIdx.y;
    int f = p % Ff;

    const float4* wrow = (const float4*)(g_w16 + ((size_t)n * Ff + f) * 16);
    float4 w0 = wrow[0], w1 = wrow[1], w2 = wrow[2], w3 = wrow[3];
    float wr[8] = {w0.x, w0.z, w1.x, w1.z, w2.x, w2.z, w3.x, w3.z};
    float wi[8] = {w0.y, w0.w, w1.y, w1.w, w2.y, w2.w, w3.y, w3.w};

    const float* mbase = mix + (size_t)n * 2 * Cc * TFv;
    float* obase = out + (size_t)n * 2 * TFv;

#pragma unroll
    for (int e = 0; e < 2; e++) {
        int pe = p + e * HTF;
        const float* base = mbase + pe;
        float Xr = 0.f, Xi = 0.f;
#pragma unroll
        for (int c = 0; c < 8; c++) {
            float yr = base[(size_t)c * TFv];
            float yv = base[(size_t)(Cc + c) * TFv];
            Xr += wr[c] * yr - wi[c] * yv;
            Xi += wr[c] * yv + wi[c] * yr;
        }
        obase[pe]       = Xr;
        obase[pe + TFv] = Xi;
    }
}

// ---------------------------------------------------------------------------
extern "C" void kernel_launch(void* const* d_in, const int* in_sizes, int n_in,
                              void* d_out, int out_size) {
    const float* mixture = (const float*)d_in[0];
    const float* noise   = (const float*)d_in[1];
    const float* sv      = (const float*)d_in[2];
    float* out = (float*)d_out;

    // 1. partial covariance over noise (dense chunk,f flattening)
    dim3 g1((GCOV + 127) / 128, Nn);
    cov_kernel<<<g1, 128>>>(noise);

    // 2. reduce chunk partials (float4)
    int rtotal4 = (Nn * 72 * Ff) / 4;
    reduce_kernel<<<(rtotal4 + 255) / 256, 256>>>();

    // 3. warp-cooperative solve: 8 lanes per (n,f)
    int sthreads = Nn * Ff * 8;
    solve_kernel<<<(sthreads + 255) / 256, 256>>>(sv);

    // 4. beamform: two elements per thread (shared weights), grid.y = n
    dim3 g4((HTF + 255) / 256, Nn);
    bf_kernel<<<g4, 256>>>(mixture, out);
}